// round 1
// baseline (speedup 1.0000x reference)
#include <cuda_runtime.h>
#include <cstdint>

#define BATCH 512
#define TSTEPS 1024
#define IDIM 64
#define HDIM 128

// Scratch (static __device__ arrays — no allocation in kernel_launch)
__device__ float g_xp[(size_t)TSTEPS * BATCH * HDIM];   // [t][b][h]  268 MB
__device__ float g_wsplat[IDIM * 2 * HDIM];             // [k][2j] duplicated W_ih for f32x2 splat loads

typedef unsigned long long u64t;

__device__ __forceinline__ u64t ffma2(u64t a, u64t b, u64t c) {
    u64t d;
    asm("fma.rn.f32x2 %0, %1, %2, %3;" : "=l"(d) : "l"(a), "l"(b), "l"(c));
    return d;
}
__device__ __forceinline__ float f2lo(u64t v) { return __uint_as_float((unsigned)(v & 0xffffffffULL)); }
__device__ __forceinline__ float f2hi(u64t v) { return __uint_as_float((unsigned)(v >> 32)); }
__device__ __forceinline__ float tanh_ap(float x) {
    float y;
    asm("tanh.approx.f32 %0, %1;" : "=f"(y) : "f"(x));
    return y;
}

// ---------------------------------------------------------------------------
// Kernel 0: build splatted W_ih:  g_wsplat[k][2j] = g_wsplat[k][2j+1] = W_ih[j][k]
// ---------------------------------------------------------------------------
__global__ void prep_kernel(const float* __restrict__ W_ih) {
    int idx = blockIdx.x * blockDim.x + threadIdx.x;
    if (idx < HDIM * IDIM) {
        int j = idx >> 6;   // 0..127
        int k = idx & 63;   // 0..63
        float v = W_ih[idx];
        *(float2*)&g_wsplat[k * 256 + 2 * j] = make_float2(v, v);
    }
}

// ---------------------------------------------------------------------------
// Kernel 1: xp[t][b][j] = sum_i x[b][t][i] * W_ih[j][i] + (b_ih[j]+b_hh[j])
// 256 threads, CTA tile = 256 rows (4 blocks of 64) x 128 cols.
// thread (cg=tid>>4, rg=tid&15): 4 rows x 8 cols, f32x2 packed over row pairs.
// ---------------------------------------------------------------------------
__global__ void __launch_bounds__(256, 2) xproj_kernel(
    const float* __restrict__ x,
    const float* __restrict__ b_ih,
    const float* __restrict__ b_hh)
{
    extern __shared__ float smem[];
    float* sW = smem;               // [64][256]  (splatted W)
    float* sX = smem + 64 * 256;    // [64][68]   (x transposed, padded)

    const int tid = threadIdx.x;
    const int cg = tid >> 4;        // 0..15 -> cols cg*8..cg*8+7
    const int rg = tid & 15;        // 0..15 -> rows rg*4..rg*4+3

    // copy splatted W into shared (conflict-free float4 copies)
    {
        const float4* src = (const float4*)g_wsplat;
        float4* dst = (float4*)sW;
        #pragma unroll
        for (int i = 0; i < 16; i++) dst[tid + 256 * i] = src[tid + 256 * i];
    }
    // per-thread bias registers (8 cols)
    float biasv[8];
    #pragma unroll
    for (int cc = 0; cc < 8; cc++) biasv[cc] = b_ih[cg * 8 + cc] + b_hh[cg * 8 + cc];

    const float* pWl = sW + cg * 16;
    const float* pXl = sX + rg * 4;

    const int m_base = blockIdx.x * 256;
    for (int blk = 0; blk < 4; blk++) {
        const int m0 = m_base + blk * 64;
        __syncthreads();
        // stage x transposed: sX[i][r] = x[(m0+r)*64 + i]
        #pragma unroll
        for (int it = 0; it < 16; it++) {
            int idx = tid + it * 256;
            int r = idx >> 6, i = idx & 63;
            sX[i * 68 + r] = x[(size_t)(m0 + r) * IDIM + i];
        }
        __syncthreads();

        u64t acc[2][8];
        #pragma unroll
        for (int a = 0; a < 2; a++)
            #pragma unroll
            for (int c = 0; c < 8; c++) acc[a][c] = 0ULL;

        #pragma unroll 8
        for (int k = 0; k < 64; k++) {
            ulonglong2 xv = *(const ulonglong2*)(pXl + k * 68);  // rows (4rg,4rg+1),(4rg+2,4rg+3)
            #pragma unroll
            for (int cp = 0; cp < 4; cp++) {
                ulonglong2 wv = *(const ulonglong2*)(pWl + k * 256 + cp * 4);  // splat(W[c]),splat(W[c+1])
                acc[0][2 * cp]     = ffma2(xv.x, wv.x, acc[0][2 * cp]);
                acc[1][2 * cp]     = ffma2(xv.y, wv.x, acc[1][2 * cp]);
                acc[0][2 * cp + 1] = ffma2(xv.x, wv.y, acc[0][2 * cp + 1]);
                acc[1][2 * cp + 1] = ffma2(xv.y, wv.y, acc[1][2 * cp + 1]);
            }
        }

        // epilogue: write xp[t][b][cols]
        #pragma unroll
        for (int rr = 0; rr < 4; rr++) {
            int m = m0 + rg * 4 + rr;
            int bb = m >> 10;          // batch
            int tt = m & 1023;         // timestep
            float* dst = g_xp + ((size_t)tt * BATCH + bb) * HDIM + cg * 8;
            int rp = rr >> 1, hi = rr & 1;
            float4 o0, o1;
            o0.x = (hi ? f2hi(acc[rp][0]) : f2lo(acc[rp][0])) + biasv[0];
            o0.y = (hi ? f2hi(acc[rp][1]) : f2lo(acc[rp][1])) + biasv[1];
            o0.z = (hi ? f2hi(acc[rp][2]) : f2lo(acc[rp][2])) + biasv[2];
            o0.w = (hi ? f2hi(acc[rp][3]) : f2lo(acc[rp][3])) + biasv[3];
            o1.x = (hi ? f2hi(acc[rp][4]) : f2lo(acc[rp][4])) + biasv[4];
            o1.y = (hi ? f2hi(acc[rp][5]) : f2lo(acc[rp][5])) + biasv[5];
            o1.z = (hi ? f2hi(acc[rp][6]) : f2lo(acc[rp][6])) + biasv[6];
            o1.w = (hi ? f2hi(acc[rp][7]) : f2lo(acc[rp][7])) + biasv[7];
            *(float4*)dst = o0;
            *(float4*)(dst + 4) = o1;
        }
    }
}

// ---------------------------------------------------------------------------
// Kernel 2: persistent recurrence. 128 CTAs x 256 threads, 4 batch rows/CTA.
// thread: warp=tid>>5, lane: kh=lane>>4 (k-half), jl=lane&15, j=warp*16+jl.
// W_hh row j (one k-half, 64 floats) lives in 32 f32x2 registers.
// h double-buffered in shared with a 4-float pad between k-halves
// (keeps the two broadcast groups of an LDS.128 on distinct banks).
// ---------------------------------------------------------------------------
__global__ void __launch_bounds__(256, 1) rnn_kernel(
    const float* __restrict__ W_hh,
    const float* __restrict__ fc_w,
    const float* __restrict__ fc_b,
    float* __restrict__ out)
{
    __shared__ __align__(16) float hbuf[2][4][136];   // [buf][b][k + 4*(k>=64)]

    const int tid = threadIdx.x;
    const int warp = tid >> 5, lane = tid & 31;
    const int kh = lane >> 4, jl = lane & 15;
    const int j = warp * 16 + jl;
    const int jphys = j + (j >= 64 ? 4 : 0);
    const int row0 = blockIdx.x * 4;

    // W_hh[j][kh*64 .. kh*64+63] -> 32 packed f32x2 registers
    u64t w[32];
    {
        const ulonglong2* src = (const ulonglong2*)(W_hh + j * HDIM + kh * 64);
        #pragma unroll
        for (int q = 0; q < 16; q++) {
            ulonglong2 v = src[q];
            w[2 * q] = v.x;
            w[2 * q + 1] = v.y;
        }
    }

    // h0 = 0
    for (int i = tid; i < 2 * 4 * 136; i += 256) ((float*)hbuf)[i] = 0.f;

    float cur[4], nxt[4];
    if (kh == 0) {
        const float* p0 = g_xp + (size_t)row0 * HDIM + j;   // t = 0
        #pragma unroll
        for (int b = 0; b < 4; b++) cur[b] = __ldg(p0 + b * HDIM);
    }
    __syncthreads();

    int p = 0;
    #pragma unroll 1
    for (int t = 0; t < TSTEPS; t++) {
        // prefetch next step's xp (consumed ~1.5 steps later -> latency hidden)
        if (kh == 0) {
            int t1 = (t + 1 < TSTEPS) ? t + 1 : t;
            const float* pn = g_xp + ((size_t)t1 * BATCH + row0) * HDIM + j;
            #pragma unroll
            for (int b = 0; b < 4; b++) nxt[b] = __ldg(pn + b * HDIM);
        }

        u64t acc[4] = {0ULL, 0ULL, 0ULL, 0ULL};
        const float* hb = &hbuf[p][0][kh * 68];
        #pragma unroll
        for (int c = 0; c < 16; c++) {
            #pragma unroll
            for (int b = 0; b < 4; b++) {
                ulonglong2 v = *(const ulonglong2*)(hb + b * 136 + c * 4);
                acc[b] = ffma2(v.x, w[2 * c], acc[b]);
                acc[b] = ffma2(v.y, w[2 * c + 1], acc[b]);
            }
        }

        #pragma unroll
        for (int b = 0; b < 4; b++) {
            float s = f2lo(acc[b]) + f2hi(acc[b]);
            s += __shfl_xor_sync(0xffffffffu, s, 16);    // combine k-halves
            if (kh == 0) {
                float h = tanh_ap(s + cur[b]);
                hbuf[p ^ 1][b][jphys] = h;
                cur[b] = nxt[b];
            }
        }
        __syncthreads();
        p ^= 1;
    }

    // fc + sigmoid epilogue: warp b handles batch row b
    if (warp < 4) {
        const int b = warp;
        float s = 0.f;
        #pragma unroll
        for (int i = lane; i < HDIM; i += 32)
            s += hbuf[p][b][i + (i >= 64 ? 4 : 0)] * fc_w[i];
        #pragma unroll
        for (int o = 16; o > 0; o >>= 1) s += __shfl_xor_sync(0xffffffffu, s, o);
        if (lane == 0) out[row0 + b] = 1.f / (1.f + __expf(-(s + fc_b[0])));
    }
}

// ---------------------------------------------------------------------------
extern "C" void kernel_launch(void* const* d_in, const int* in_sizes, int n_in,
                              void* d_out, int out_size)
{
    const float* x    = (const float*)d_in[0];
    const float* W_ih = (const float*)d_in[1];
    const float* W_hh = (const float*)d_in[2];
    const float* b_ih = (const float*)d_in[3];
    const float* b_hh = (const float*)d_in[4];
    const float* fc_w = (const float*)d_in[5];
    const float* fc_b = (const float*)d_in[6];
    float* out = (float*)d_out;

    const int smem_bytes = (64 * 256 + 64 * 68) * 4;   // 82944
    cudaFuncSetAttribute(xproj_kernel, cudaFuncAttributeMaxDynamicSharedMemorySize, smem_bytes);

    prep_kernel<<<32, 256>>>(W_ih);
    xproj_kernel<<<2048, 256, smem_bytes>>>(x, b_ih, b_hh);
    rnn_kernel<<<128, 256>>>(W_hh, fc_w, fc_b, out);
}